// round 2
// baseline (speedup 1.0000x reference)
#include <cuda_runtime.h>
#include <cuda_bf16.h>
#include <math_constants.h>

// Shapes (fixed by the problem)
#define HIDDEN    2048
#define NUM_HEADS 16
#define HEAD_DIM  128
#define NUM_SEQS  64
#define MAX_BLOCKS 32
#define NUM_BLOCKS 2048
#define BLOCK_SIZE 64
#define KSPLIT 4

// Scratch (allocation-free rule: __device__ globals)
__device__ float g_part[KSPLIT * NUM_SEQS * HIDDEN];  // split-K partials (2MB)
__device__ float g_q[NUM_SEQS * HIDDEN];              // scaled Q
__device__ float g_attn[NUM_SEQS * HIDDEN];           // attention output

// ---------------------------------------------------------------------------
// Split-K GEMM: C_partial[ks] = A[64 x Kslice] * B[Kslice x 64cols-tile]
// A is 64 x 2048 row-major (lda=2048). B row-major with given ldb.
// Tile: M=64, N=64, K=32. 256 threads, 4x4 micro-tile per thread.
// Grid: (HIDDEN/64, KSPLIT)
// ---------------------------------------------------------------------------
__global__ __launch_bounds__(256) void gemm_splitk(
    const float* __restrict__ Ain,   // nullptr -> g_attn
    const float* __restrict__ B,
    int ldb)
{
    const float* A = Ain ? Ain : g_attn;
    const int n0 = blockIdx.x * 64;
    const int ks = blockIdx.y;
    const int k_begin = ks * (HIDDEN / KSPLIT);   // 512 per slice

    __shared__ float As[64 * 36];  // [m][36] padded rows, float4-aligned
    __shared__ float Bs[32 * 64];  // [k][n]

    const int tid = threadIdx.x;
    const int tm = (tid / 16) * 4;       // 0..60
    const int tn = (tid % 16) * 4;       // 0..60

    float acc[4][4];
#pragma unroll
    for (int i = 0; i < 4; i++)
#pragma unroll
        for (int j = 0; j < 4; j++) acc[i][j] = 0.f;

    const int ar = tid / 8;        // 0..31
    const int ac = (tid % 8) * 4;  // 0..28
    const int bk = tid / 16;       // 0..15
    const int bn = (tid % 16) * 4; // 0..60

    for (int kt = 0; kt < (HIDDEN / KSPLIT) / 32; kt++) {
        const int k0 = k_begin + kt * 32;
        // global loads (registers) before the barrier
        float4 a0 = *(const float4*)&A[ar * HIDDEN + k0 + ac];
        float4 a1 = *(const float4*)&A[(ar + 32) * HIDDEN + k0 + ac];
        float4 b0 = *(const float4*)&B[(size_t)(k0 + bk) * ldb + n0 + bn];
        float4 b1 = *(const float4*)&B[(size_t)(k0 + bk + 16) * ldb + n0 + bn];

        __syncthreads();  // previous tile fully consumed
        *(float4*)&As[ar * 36 + ac]        = a0;
        *(float4*)&As[(ar + 32) * 36 + ac] = a1;
        *(float4*)&Bs[bk * 64 + bn]        = b0;
        *(float4*)&Bs[(bk + 16) * 64 + bn] = b1;
        __syncthreads();

#pragma unroll
        for (int kk = 0; kk < 32; kk++) {
            float4 b4 = *(const float4*)&Bs[kk * 64 + tn];
            float a_0 = As[(tm + 0) * 36 + kk];
            float a_1 = As[(tm + 1) * 36 + kk];
            float a_2 = As[(tm + 2) * 36 + kk];
            float a_3 = As[(tm + 3) * 36 + kk];
            acc[0][0] += a_0 * b4.x; acc[0][1] += a_0 * b4.y; acc[0][2] += a_0 * b4.z; acc[0][3] += a_0 * b4.w;
            acc[1][0] += a_1 * b4.x; acc[1][1] += a_1 * b4.y; acc[1][2] += a_1 * b4.z; acc[1][3] += a_1 * b4.w;
            acc[2][0] += a_2 * b4.x; acc[2][1] += a_2 * b4.y; acc[2][2] += a_2 * b4.z; acc[2][3] += a_2 * b4.w;
            acc[3][0] += a_3 * b4.x; acc[3][1] += a_3 * b4.y; acc[3][2] += a_3 * b4.z; acc[3][3] += a_3 * b4.w;
        }
    }

    float* P = g_part + (size_t)ks * NUM_SEQS * HIDDEN + n0 + tn;
#pragma unroll
    for (int j = 0; j < 4; j++) {
        float4 o = make_float4(acc[j][0], acc[j][1], acc[j][2], acc[j][3]);
        *(float4*)&P[(tm + j) * HIDDEN] = o;
    }
}

// ---------------------------------------------------------------------------
// Reduce split-K partials, add bias, multiply by mul.
// outp == nullptr -> write g_q. Grid: 64*2048/256 = 512 blocks.
// ---------------------------------------------------------------------------
__global__ __launch_bounds__(256) void reduce_bias(
    const float* __restrict__ bias, float* __restrict__ outp, float mul)
{
    float* dst = outp ? outp : g_q;
    int idx = blockIdx.x * 256 + threadIdx.x;
    int n = idx & (HIDDEN - 1);
    float s = bias[n];
#pragma unroll
    for (int i = 0; i < KSPLIT; i++)
        s += g_part[i * NUM_SEQS * HIDDEN + idx];
    dst[idx] = s * mul;
}

// ---------------------------------------------------------------------------
// Paged decode attention. Grid (NUM_HEADS, NUM_SEQS), 256 threads (8 warps).
// Each warp handles tokens t = w, w+8, ... with an online softmax; one
// float4 per lane covers the 128-dim head. 1-token software prefetch for MLP.
// ---------------------------------------------------------------------------
__global__ __launch_bounds__(256) void attn_kernel(
    const float* __restrict__ kv,
    const int*   __restrict__ bt,
    const int*   __restrict__ sl)
{
    const int head = blockIdx.x;
    const int seq  = blockIdx.y;
    const int tid  = threadIdx.x;
    const int lane = tid & 31;
    const int w    = tid >> 5;

    __shared__ int   sbt[MAX_BLOCKS];
    __shared__ float sm[8], sls[8];
    __shared__ float sacc[8][HEAD_DIM];

    if (tid < MAX_BLOCKS) sbt[tid] = bt[seq * MAX_BLOCKS + tid];
    __syncthreads();

    const int len = sl[seq];
    const float4 q4 = *(const float4*)&g_q[seq * HIDDEN + head * HEAD_DIM + lane * 4];
    const float* Kc = kv;
    const float* Vc = kv + (size_t)NUM_BLOCKS * BLOCK_SIZE * NUM_HEADS * HEAD_DIM;

    float m = -CUDART_INF_F, l = 0.f;
    float4 acc = make_float4(0.f, 0.f, 0.f, 0.f);

    int t = w;
    if (t < len) {
        size_t base = ((size_t)(sbt[t >> 6] * BLOCK_SIZE + (t & 63)) * NUM_HEADS + head) * HEAD_DIM;
        float4 k4 = *(const float4*)&Kc[base + lane * 4];
        float4 v4 = *(const float4*)&Vc[base + lane * 4];
        for (;;) {
            const int t2 = t + 8;
            const bool more = t2 < len;
            float4 k4n, v4n;
            if (more) {
                size_t b2 = ((size_t)(sbt[t2 >> 6] * BLOCK_SIZE + (t2 & 63)) * NUM_HEADS + head) * HEAD_DIM;
                k4n = *(const float4*)&Kc[b2 + lane * 4];
                v4n = *(const float4*)&Vc[b2 + lane * 4];
            }
            float d = q4.x * k4.x + q4.y * k4.y + q4.z * k4.z + q4.w * k4.w;
            d += __shfl_xor_sync(0xffffffffu, d, 16);
            d += __shfl_xor_sync(0xffffffffu, d, 8);
            d += __shfl_xor_sync(0xffffffffu, d, 4);
            d += __shfl_xor_sync(0xffffffffu, d, 2);
            d += __shfl_xor_sync(0xffffffffu, d, 1);
            const float mn = fmaxf(m, d);
            const float c  = __expf(m - mn);   // exp(-inf)=0 on first iter
            const float p  = __expf(d - mn);
            l = l * c + p;
            acc.x = acc.x * c + p * v4.x;
            acc.y = acc.y * c + p * v4.y;
            acc.z = acc.z * c + p * v4.z;
            acc.w = acc.w * c + p * v4.w;
            m = mn;
            if (!more) break;
            t = t2; k4 = k4n; v4 = v4n;
        }
    }

    if (lane == 0) { sm[w] = m; sls[w] = l; }
    *(float4*)&sacc[w][lane * 4] = acc;
    __syncthreads();

    if (tid < HEAD_DIM) {
        float M = sm[0];
#pragma unroll
        for (int i = 1; i < 8; i++) M = fmaxf(M, sm[i]);
        float L = 0.f, o = 0.f;
#pragma unroll
        for (int i = 0; i < 8; i++) {
            float c = __expf(sm[i] - M);   // empty warps: exp(-inf-M)=0
            L += sls[i] * c;
            o += sacc[i][tid] * c;
        }
        g_attn[seq * HIDDEN + head * HEAD_DIM + tid] = o / L;
    }
}

// ---------------------------------------------------------------------------
extern "C" void kernel_launch(void* const* d_in, const int* in_sizes, int n_in,
                              void* d_out, int out_size)
{
    const float* hidden  = (const float*)d_in[0];
    // const float* kv   = d_in[1]
    const float* W_attn  = (const float*)d_in[2];
    const float* b_attn  = (const float*)d_in[3];
    const float* W_proj  = (const float*)d_in[4];
    const float* b_proj  = (const float*)d_in[5];
    const int*   bt      = (const int*)d_in[6];
    const int*   slens   = (const int*)d_in[7];
    const float* kv      = (const float*)d_in[1];
    float* out = (float*)d_out;

    const float SCALE = 0.08838834764831845f;  // 128^-0.5

    // Q = (hidden @ W_attn[:, :2048] + b_attn[:2048]) * SCALE
    gemm_splitk<<<dim3(HIDDEN / 64, KSPLIT), 256>>>(hidden, W_attn, 3 * HIDDEN);
    reduce_bias<<<NUM_SEQS * HIDDEN / 256, 256>>>(b_attn, nullptr, SCALE);

    // Paged attention
    attn_kernel<<<dim3(NUM_HEADS, NUM_SEQS), 256>>>(kv, bt, slens);

    // out = attn @ W_proj + b_proj
    gemm_splitk<<<dim3(HIDDEN / 64, KSPLIT), 256>>>(nullptr, W_proj, HIDDEN);
    reduce_bias<<<NUM_SEQS * HIDDEN / 256, 256>>>(b_proj, out, 1.0f);
}

// round 5
// speedup vs baseline: 1.1712x; 1.1712x over previous
#include <cuda_runtime.h>
#include <cuda_bf16.h>
#include <math_constants.h>

// Shapes (fixed by the problem)
#define HIDDEN    2048
#define NUM_HEADS 16
#define HEAD_DIM  128
#define NUM_SEQS  64
#define MAX_BLOCKS 32
#define NUM_BLOCKS 2048
#define BLOCK_SIZE 64
#define KSPLIT 4
#define CHUNK  128            // split-KV chunk (2 cache blocks)
#define MAX_CHUNKS 16         // 2048 / 128

// Scratch (allocation-free rule: __device__ globals)
__device__ float g_part[KSPLIT * NUM_SEQS * HIDDEN];                       // split-K GEMM partials
__device__ float g_q[NUM_SEQS * HIDDEN];                                   // scaled Q
__device__ float g_attn[NUM_SEQS * HIDDEN];                                // attention output
__device__ float g_pacc[NUM_SEQS * NUM_HEADS * MAX_CHUNKS * HEAD_DIM];     // split-KV partial acc (8MB)
__device__ float g_pm[NUM_SEQS * NUM_HEADS * MAX_CHUNKS];                  // partial max
__device__ float g_pl[NUM_SEQS * NUM_HEADS * MAX_CHUNKS];                  // partial sum

// ---------------------------------------------------------------------------
// Split-K GEMM, double-buffered smem, single sync per K-tile.
// C_partial[ks] = A[64 x 512-slice] * B[512-slice x 64col-tile]
// Tile: M=64, N=64, Kt=32. 256 threads, 4x4 micro-tile. Grid (32, KSPLIT).
// ---------------------------------------------------------------------------
__global__ __launch_bounds__(256) void gemm_splitk(
    const float* __restrict__ Ain,   // nullptr -> g_attn
    const float* __restrict__ B,
    int ldb)
{
    const float* A = Ain ? Ain : g_attn;
    const int n0 = blockIdx.x * 64;
    const int ks = blockIdx.y;
    const int k_begin = ks * (HIDDEN / KSPLIT);   // 512 per slice
    const int KT = (HIDDEN / KSPLIT) / 32;        // 16 K-tiles

    __shared__ float As[2][64 * 36];  // padded rows
    __shared__ float Bs[2][32 * 64];

    const int tid = threadIdx.x;
    const int tm = (tid / 16) * 4;
    const int tn = (tid % 16) * 4;

    float acc[4][4];
#pragma unroll
    for (int i = 0; i < 4; i++)
#pragma unroll
        for (int j = 0; j < 4; j++) acc[i][j] = 0.f;

    const int ar = tid / 8;        // 0..31
    const int ac = (tid % 8) * 4;  // 0..28
    const int bk = tid / 16;       // 0..15
    const int bn = (tid % 16) * 4; // 0..60

    // prologue: load tile 0 into registers
    float4 a0 = *(const float4*)&A[ar * HIDDEN + k_begin + ac];
    float4 a1 = *(const float4*)&A[(ar + 32) * HIDDEN + k_begin + ac];
    float4 b0 = *(const float4*)&B[(size_t)(k_begin + bk) * ldb + n0 + bn];
    float4 b1 = *(const float4*)&B[(size_t)(k_begin + bk + 16) * ldb + n0 + bn];

    for (int kt = 0; kt < KT; kt++) {
        const int buf = kt & 1;
        // store current tile (written to buffer last used 2 iterations ago;
        // the single barrier below in the PREVIOUS iteration ordered those reads)
        *(float4*)&As[buf][ar * 36 + ac]        = a0;
        *(float4*)&As[buf][(ar + 32) * 36 + ac] = a1;
        *(float4*)&Bs[buf][bk * 64 + bn]        = b0;
        *(float4*)&Bs[buf][(bk + 16) * 64 + bn] = b1;
        __syncthreads();

        // issue next tile's global loads (overlap with compute below)
        if (kt + 1 < KT) {
            const int k0 = k_begin + (kt + 1) * 32;
            a0 = *(const float4*)&A[ar * HIDDEN + k0 + ac];
            a1 = *(const float4*)&A[(ar + 32) * HIDDEN + k0 + ac];
            b0 = *(const float4*)&B[(size_t)(k0 + bk) * ldb + n0 + bn];
            b1 = *(const float4*)&B[(size_t)(k0 + bk + 16) * ldb + n0 + bn];
        }

#pragma unroll
        for (int kk = 0; kk < 32; kk++) {
            float4 b4 = *(const float4*)&Bs[buf][kk * 64 + tn];
            float a_0 = As[buf][(tm + 0) * 36 + kk];
            float a_1 = As[buf][(tm + 1) * 36 + kk];
            float a_2 = As[buf][(tm + 2) * 36 + kk];
            float a_3 = As[buf][(tm + 3) * 36 + kk];
            acc[0][0] += a_0 * b4.x; acc[0][1] += a_0 * b4.y; acc[0][2] += a_0 * b4.z; acc[0][3] += a_0 * b4.w;
            acc[1][0] += a_1 * b4.x; acc[1][1] += a_1 * b4.y; acc[1][2] += a_1 * b4.z; acc[1][3] += a_1 * b4.w;
            acc[2][0] += a_2 * b4.x; acc[2][1] += a_2 * b4.y; acc[2][2] += a_2 * b4.z; acc[2][3] += a_2 * b4.w;
            acc[3][0] += a_3 * b4.x; acc[3][1] += a_3 * b4.y; acc[3][2] += a_3 * b4.z; acc[3][3] += a_3 * b4.w;
        }
    }

    float* P = g_part + (size_t)ks * NUM_SEQS * HIDDEN + n0 + tn;
#pragma unroll
    for (int j = 0; j < 4; j++) {
        float4 o = make_float4(acc[j][0], acc[j][1], acc[j][2], acc[j][3]);
        *(float4*)&P[(tm + j) * HIDDEN] = o;
    }
}

// ---------------------------------------------------------------------------
// Reduce split-K partials, add bias, multiply by mul.
// ---------------------------------------------------------------------------
__global__ __launch_bounds__(256) void reduce_bias(
    const float* __restrict__ bias, float* __restrict__ outp, float mul)
{
    float* dst = outp ? outp : g_q;
    int idx = blockIdx.x * 256 + threadIdx.x;
    int n = idx & (HIDDEN - 1);
    float s = bias[n];
#pragma unroll
    for (int i = 0; i < KSPLIT; i++)
        s += g_part[i * NUM_SEQS * HIDDEN + idx];
    dst[idx] = s * mul;
}

// ---------------------------------------------------------------------------
// Split-KV paged attention, phase 1: per-chunk partial softmax.
// Grid (NUM_HEADS, NUM_SEQS, MAX_CHUNKS), 256 threads (8 warps).
// Each chunk = 128 tokens = exactly 2 KV-cache blocks. Depth-2 prefetch.
// ---------------------------------------------------------------------------
__global__ __launch_bounds__(256) void attn_chunk(
    const float* __restrict__ kv,
    const int*   __restrict__ bt,
    const int*   __restrict__ sl)
{
    const int head  = blockIdx.x;
    const int seq   = blockIdx.y;
    const int chunk = blockIdx.z;

    const int len = sl[seq];
    const int t0  = chunk * CHUNK;
    if (t0 >= len) return;                         // early-exit: no work
    const int tend = min(t0 + CHUNK, len);

    const int tid  = threadIdx.x;
    const int lane = tid & 31;
    const int w    = tid >> 5;

    // chunk spans exactly cache blocks 2*chunk and 2*chunk+1 (broadcast LDG)
    const int b0 = bt[seq * MAX_BLOCKS + 2 * chunk];
    const int b1 = bt[seq * MAX_BLOCKS + 2 * chunk + 1];

    __shared__ float sm[8], sls[8];
    __shared__ float sacc[8][HEAD_DIM];

    const float4 q4 = *(const float4*)&g_q[seq * HIDDEN + head * HEAD_DIM + lane * 4];
    const float* Kc = kv;
    const float* Vc = kv + (size_t)NUM_BLOCKS * BLOCK_SIZE * NUM_HEADS * HEAD_DIM;

    float m = -CUDART_INF_F, l = 0.f;
    float4 acc = make_float4(0.f, 0.f, 0.f, 0.f);

    int t = t0 + w;
    if (t < tend) {
        // address helper: token t -> byte base for this head
        auto addr = [&](int tt) -> size_t {
            int local = tt - t0;
            int blk = (local < 64) ? b0 : b1;
            return ((size_t)(blk * BLOCK_SIZE + (tt & 63)) * NUM_HEADS + head) * HEAD_DIM;
        };

        size_t ba = addr(t);
        float4 k0 = *(const float4*)&Kc[ba + lane * 4];
        float4 v0 = *(const float4*)&Vc[ba + lane * 4];
        int   t1 = t + 8;
        bool  h1 = t1 < tend;
        float4 k1, v1;
        if (h1) {
            size_t b2 = addr(t1);
            k1 = *(const float4*)&Kc[b2 + lane * 4];
            v1 = *(const float4*)&Vc[b2 + lane * 4];
        }
        for (;;) {
            // prefetch depth-2
            const int t2 = t + 16;
            const bool h2 = t2 < tend;
            float4 k2, v2;
            if (h2) {
                size_t b3 = addr(t2);
                k2 = *(const float4*)&Kc[b3 + lane * 4];
                v2 = *(const float4*)&Vc[b3 + lane * 4];
            }
            // dot + warp reduce
            float d = q4.x * k0.x + q4.y * k0.y + q4.z * k0.z + q4.w * k0.w;
            d += __shfl_xor_sync(0xffffffffu, d, 16);
            d += __shfl_xor_sync(0xffffffffu, d, 8);
            d += __shfl_xor_sync(0xffffffffu, d, 4);
            d += __shfl_xor_sync(0xffffffffu, d, 2);
            d += __shfl_xor_sync(0xffffffffu, d, 1);
            const float mn = fmaxf(m, d);
            const float c  = __expf(m - mn);
            const float p  = __expf(d - mn);
            l = l * c + p;
            acc.x = acc.x * c + p * v0.x;
            acc.y = acc.y * c + p * v0.y;
            acc.z = acc.z * c + p * v0.z;
            acc.w = acc.w * c + p * v0.w;
            m = mn;
            if (!h1) break;
            t += 8;
            k0 = k1; v0 = v1;
            h1 = h2; k1 = k2; v1 = v2;
        }
    }

    if (lane == 0) { sm[w] = m; sls[w] = l; }
    *(float4*)&sacc[w][lane * 4] = acc;
    __syncthreads();

    if (tid < HEAD_DIM) {
        float M = sm[0];
#pragma unroll
        for (int i = 1; i < 8; i++) M = fmaxf(M, sm[i]);
        float L = 0.f, o = 0.f;
#pragma unroll
        for (int i = 0; i < 8; i++) {
            float c = __expf(sm[i] - M);   // idle warps (m=-inf) contribute 0
            L += sls[i] * c;
            o += sacc[i][tid] * c;
        }
        const int idx = (seq * NUM_HEADS + head) * MAX_CHUNKS + chunk;
        g_pacc[(size_t)idx * HEAD_DIM + tid] = o;   // unnormalized
        if (tid == 0) { g_pm[idx] = M; g_pl[idx] = L; }
    }
}

// ---------------------------------------------------------------------------
// Split-KV phase 2: combine chunk partials. Grid 1024, 128 threads.
// ---------------------------------------------------------------------------
__global__ __launch_bounds__(128) void attn_combine(const int* __restrict__ sl)
{
    const int sh   = blockIdx.x;            // seq*16 + head
    const int seq  = sh >> 4;
    const int head = sh & 15;
    const int tid  = threadIdx.x;

    const int len = sl[seq];
    const int nc  = (len + CHUNK - 1) / CHUNK;

    float M = -CUDART_INF_F, L = 0.f, o = 0.f;
    for (int c = 0; c < nc; c++) {
        const int idx = sh * MAX_CHUNKS + c;
        const float mc = g_pm[idx];
        const float lc = g_pl[idx];
        const float a  = g_pacc[(size_t)idx * HEAD_DIM + tid];
        const float mn = fmaxf(M, mc);
        const float corr = __expf(M - mn);   // first iter: exp(-inf)=0
        const float cc   = __expf(mc - mn);
        L = L * corr + lc * cc;
        o = o * corr + a * cc;
        M = mn;
    }
    g_attn[seq * HIDDEN + head * HEAD_DIM + tid] = o / L;
}

// ---------------------------------------------------------------------------
extern "C" void kernel_launch(void* const* d_in, const int* in_sizes, int n_in,
                              void* d_out, int out_size)
{
    const float* hidden  = (const float*)d_in[0];
    const float* kv      = (const float*)d_in[1];
    const float* W_attn  = (const float*)d_in[2];
    const float* b_attn  = (const float*)d_in[3];
    const float* W_proj  = (const float*)d_in[4];
    const float* b_proj  = (const float*)d_in[5];
    const int*   bt      = (const int*)d_in[6];
    const int*   slens   = (const int*)d_in[7];
    float* out = (float*)d_out;

    const float SCALE = 0.08838834764831845f;  // 128^-0.5

    // Q = (hidden @ W_attn[:, :2048] + b_attn[:2048]) * SCALE
    gemm_splitk<<<dim3(HIDDEN / 64, KSPLIT), 256>>>(hidden, W_attn, 3 * HIDDEN);
    reduce_bias<<<NUM_SEQS * HIDDEN / 256, 256>>>(b_attn, nullptr, SCALE);

    // Split-KV paged attention
    attn_chunk<<<dim3(NUM_HEADS, NUM_SEQS, MAX_CHUNKS), 256>>>(kv, bt, slens);
    attn_combine<<<NUM_SEQS * NUM_HEADS, 128>>>(slens);

    // out = attn @ W_proj + b_proj
    gemm_splitk<<<dim3(HIDDEN / 64, KSPLIT), 256>>>(nullptr, W_proj, HIDDEN);
    reduce_bias<<<NUM_SEQS * HIDDEN / 256, 256>>>(b_proj, out, 1.0f);
}